// round 14
// baseline (speedup 1.0000x reference)
#include <cuda_runtime.h>

#define NB 8
#define NC 3
#define NH 512
#define NW 512
#define HP 514
#define WP 514
#define BX 32
#define BY 16
#define NT 512                // 32x16 threads

// shared tile dims
#define TX (BX + 6)           // 38
#define TY (BY + 6)           // 22
#define RX (BX + 4)           // 36
#define RY (BY + 4)           // 20
#define MX (BX + 2)           // 34
#define MY (BY + 2)           // 18

// (0.5/var_ddof1)*log2e numerator: 4*log2e
#define CEXP 5.770780163555854f

struct alignas(16) Smem {
    float  sp[NC][TY][TX];     // img_p tile            (10032 B)
    float  usum[TY][TX];       // channel sum of sp     (3344 B)
    float  sr[RY][RX];         // img_r                 (2880 B)  -> sstat at 16256 (16B aligned)
    float2 sstat[NC][RY][RX];  // (mean, a)             (17280 B)
    float  sm[MY][MX];         // img_3d_mod            (2448 B)
};                             // ~35.1 KB

// raw 2^x (MUFU.EX2); exp(-z) == ex2(-z*log2e), log2e folded into 'a'
static __device__ __forceinline__ float ex2f(float x)
{
    float r; asm("ex2.approx.f32 %0, %1;" : "=f"(r) : "f"(x)); return r;
}

// stage A: one PAIR of horizontally-adjacent img_r pixels (lx even)
template<bool IN>
static __device__ __forceinline__ void stageA2(Smem& S, int p, int by, int bx)
{
    int ly = p / (RX / 2);
    int lx = (p - ly * (RX / 2)) * 2;
    bool in0 = true, in1 = true;
    if (!IN) {
        int hh = by - 2 + ly, ww = bx - 2 + lx;
        bool hok = (hh >= 0 && hh < NH);
        in0 = hok && (ww >= 0) && (ww < NW);
        in1 = hok && (ww + 1 >= 0) && (ww + 1 < NW);
    }
    float zmax0[9], zmax1[9];
    #pragma unroll
    for (int c = 0; c < NC; c++) {
        float2 ra[3], rb[3];                 // window cols lx..lx+3, rows ly..ly+2
        #pragma unroll
        for (int i = 0; i < 3; i++) {
            ra[i] = *(const float2*)&S.sp[c][ly + i][lx];
            rb[i] = *(const float2*)&S.sp[c][ly + i][lx + 2];
        }
        float s0 = 0.f, ss0 = 0.f, s1 = 0.f, ss1 = 0.f;
        #pragma unroll
        for (int i = 0; i < 3; i++) {
            float c0 = ra[i].x, c1 = ra[i].y, c2 = rb[i].x, c3 = rb[i].y;
            s0 += c0 + c1 + c2;
            ss0 = fmaf(c0, c0, fmaf(c1, c1, fmaf(c2, c2, ss0)));
            s1 += c1 + c2 + c3;
            ss1 = fmaf(c1, c1, fmaf(c2, c2, fmaf(c3, c3, ss1)));
        }
        float mn0 = s0 * (1.f / 9.f), mn1 = s1 * (1.f / 9.f);
        float a0 = __fdividef(CEXP, fmaf(-s0, mn0, ss0));
        float a1 = __fdividef(CEXP, fmaf(-s1, mn1, ss1));
        *(float4*)&S.sstat[c][ly][lx] = make_float4(mn0, a0, mn1, a1); // STS.128
        #pragma unroll
        for (int i = 0; i < 3; i++) {
            float c0 = ra[i].x, c1 = ra[i].y, c2 = rb[i].x, c3 = rb[i].y;
            float d, z;
            d = c0 - mn0; z = d * d * a0;
            zmax0[i*3+0] = (c == 0) ? z : fmaxf(zmax0[i*3+0], z);
            d = c1 - mn0; z = d * d * a0;
            zmax0[i*3+1] = (c == 0) ? z : fmaxf(zmax0[i*3+1], z);
            d = c2 - mn0; z = d * d * a0;
            zmax0[i*3+2] = (c == 0) ? z : fmaxf(zmax0[i*3+2], z);
            d = c1 - mn1; z = d * d * a1;
            zmax1[i*3+0] = (c == 0) ? z : fmaxf(zmax1[i*3+0], z);
            d = c2 - mn1; z = d * d * a1;
            zmax1[i*3+1] = (c == 0) ? z : fmaxf(zmax1[i*3+1], z);
            d = c3 - mn1; z = d * d * a1;
            zmax1[i*3+2] = (c == 0) ? z : fmaxf(zmax1[i*3+2], z);
        }
    }
    float num0 = 0.f, den0 = 0.f, num1 = 0.f, den1 = 0.f;
    #pragma unroll
    for (int i = 0; i < 3; i++) {
        float2 ua = *(const float2*)&S.usum[ly + i][lx];
        float2 ub = *(const float2*)&S.usum[ly + i][lx + 2];
        float m;
        m = ex2f(-zmax0[i*3+0]); den0 += m; num0 = fmaf(ua.x, m, num0);
        m = ex2f(-zmax0[i*3+1]); den0 += m; num0 = fmaf(ua.y, m, num0);
        m = ex2f(-zmax0[i*3+2]); den0 += m; num0 = fmaf(ub.x, m, num0);
        m = ex2f(-zmax1[i*3+0]); den1 += m; num1 = fmaf(ua.y, m, num1);
        m = ex2f(-zmax1[i*3+1]); den1 += m; num1 = fmaf(ub.x, m, num1);
        m = ex2f(-zmax1[i*3+2]); den1 += m; num1 = fmaf(ub.y, m, num1);
    }
    float rv0 = in0 ? __fdividef(num0, den0) : 0.f;
    float rv1 = in1 ? __fdividef(num1, den1) : 0.f;
    *(float2*)&S.sr[ly][lx] = make_float2(rv0, rv1);                   // STS.64
}

// stage B: one PAIR of mod pixels (lx even)
template<bool IN>
static __device__ __forceinline__ void stageB2(Smem& S, int q, int by, int bx, int mix)
{
    int ly = q / (MX / 2);
    int lx = (q - ly * (MX / 2)) * 2;
    bool in0 = true, in1 = true;
    if (!IN) {
        int hh = by - 1 + ly, ww = bx - 1 + lx;
        bool hok = (hh >= 0 && hh < NH);
        in0 = hok && (ww >= 0) && (ww < NW);
        in1 = hok && (ww + 1 >= 0) && (ww + 1 < NW);
    }
    float2 ta[3], tb[3];                     // sr cols lx..lx+3, rows ly..ly+2
    #pragma unroll
    for (int i = 0; i < 3; i++) {
        ta[i] = *(const float2*)&S.sr[ly + i][lx];
        tb[i] = *(const float2*)&S.sr[ly + i][lx + 2];
    }
    // first-occurrence argmin/argmax for both pixels (k ascending, strict cmp)
    float v0, vmin0, vmax0, vmin1, vmax1;
    int imin0 = 0, imax0 = 0, imin1 = 0, imax1 = 0;
    vmin0 = vmax0 = ta[0].x;
    vmin1 = vmax1 = ta[0].y;
    #pragma unroll
    for (int k = 1; k < 9; k++) {
        int i = k / 3, j = k % 3;
        v0 = (j == 0) ? ta[i].x : ((j == 1) ? ta[i].y : tb[i].x);
        float v1 = (j == 0) ? ta[i].y : ((j == 1) ? tb[i].x : tb[i].y);
        if (v0 < vmin0) { vmin0 = v0; imin0 = k; }
        if (v0 > vmax0) { vmax0 = v0; imax0 = k; }
        if (v1 < vmin1) { vmin1 = v1; imin1 = k; }
        if (v1 > vmax1) { vmax1 = v1; imax1 = k; }
    }
    int ids0 = mix ? imax0 : imin0;
    int ids1 = mix ? imax1 : imin1;
    int ki0 = ids0 / 3, kj0 = ids0 % 3;
    int ki1 = ids1 / 3, kj1 = ids1 % 3;
    float zm0 = 0.f, zm1 = 0.f;
    #pragma unroll
    for (int c = 0; c < NC; c++) {
        float2 st0 = S.sstat[c][ly + 1][lx + 1];
        float2 st1 = S.sstat[c][ly + 1][lx + 2];
        float d0 = S.sp[c][ly + 1 + ki0][lx + 1 + kj0] - st0.x;
        zm0 = fmaxf(zm0, d0 * d0 * st0.y);
        float d1 = S.sp[c][ly + 1 + ki1][lx + 2 + kj1] - st1.x;
        zm1 = fmaxf(zm1, d1 * d1 * st1.y);
    }
    float mv0 = in0 ? ex2f(-zm0) : 0.f;
    float mv1 = in1 ? ex2f(-zm1) : 0.f;
    *(float2*)&S.sm[ly][lx] = make_float2(mv0, mv1);                   // STS.64
}

template<bool IN>
static __device__ __forceinline__ void run_tile(
    Smem& S, int b, int by, int bx, int tid, int mix,
    const float* __restrict__ img, const float* __restrict__ noise,
    const float* __restrict__ re, float* __restrict__ out)
{
    // ---- load img_p tile, pixel-major: all 3 channels + usum per item ----
    for (int i = tid; i < TY * TX; i += NT) {
        int ly = i / TX, lx = i - ly * TX;
        int yp = by - 2 + ly, xp = bx - 2 + lx;
        float v0, v1, v2;
        if (IN) {
            int nbase = ((b * NC) * HP + yp) * WP + xp;
            int ibase = ((b * NC) * NH + (yp - 1)) * NW + (xp - 1);
            v0 = noise[nbase             ] + img[ibase            ];
            v1 = noise[nbase +     HP*WP ] + img[ibase +     NH*NW];
            v2 = noise[nbase + 2 * HP*WP ] + img[ibase + 2 * NH*NW];
        } else {
            v0 = v1 = v2 = 0.f;
            if (yp >= 0 && yp < HP && xp >= 0 && xp < WP) {
                int nbase = ((b * NC) * HP + yp) * WP + xp;
                v0 = noise[nbase];
                v1 = noise[nbase + HP*WP];
                v2 = noise[nbase + 2 * HP*WP];
                if (yp >= 1 && yp <= NH && xp >= 1 && xp <= NW) {
                    int ibase = ((b * NC) * NH + (yp - 1)) * NW + (xp - 1);
                    v0 += img[ibase];
                    v1 += img[ibase + NH*NW];
                    v2 += img[ibase + 2 * NH*NW];
                }
            }
        }
        S.sp[0][ly][lx] = v0;
        S.sp[1][ly][lx] = v1;
        S.sp[2][ly][lx] = v2;
        S.usum[ly][lx]  = v0 + v1 + v2;
    }
    __syncthreads();

    // ---- stage A: 360 pixel-pairs, single pass ----
    if (tid < (RY * RX) / 2) stageA2<IN>(S, tid, by, bx);
    __syncthreads();

    // ---- stage B: 306 pixel-pairs, single pass ----
    if (tid < (MY * MX) / 2) stageB2<IN>(S, tid, by, bx, mix);
    __syncthreads();

    // ---- stage C: 256 pixel-pairs, float2 smem + gmem I/O ----
    if (tid < (BX / 2) * BY) {
        int ty  = tid >> 4;           // 0..15
        int tx2 = (tid & 15) * 2;     // even column 0..30
        float2 ma[3], mb[3];
        #pragma unroll
        for (int i = 0; i < 3; i++) {
            ma[i] = *(const float2*)&S.sm[ty + i][tx2];
            mb[i] = *(const float2*)&S.sm[ty + i][tx2 + 2];
        }
        float den0 = 0.f, den1 = 0.f;
        #pragma unroll
        for (int i = 0; i < 3; i++) {
            den0 += ma[i].x + ma[i].y + mb[i].x;
            den1 += ma[i].y + mb[i].x + mb[i].y;
        }
        float id0 = __fdividef(1.f, den0);
        float id1 = __fdividef(1.f, den1);
        const int h = by + ty, w = bx + tx2;
        #pragma unroll
        for (int c = 0; c < NC; c++) {
            float n0 = 0.f, n1 = 0.f;
            #pragma unroll
            for (int i = 0; i < 3; i++) {
                float2 p = *(const float2*)&S.sp[c][ty + 2 + i][tx2 + 2];
                float2 q = *(const float2*)&S.sp[c][ty + 2 + i][tx2 + 4];
                float t1 = p.y * ma[i].y;
                float t2 = q.x * mb[i].x;
                n0 += fmaf(p.x, ma[i].x, t1 + t2);
                n1 += fmaf(q.y, mb[i].y, t1 + t2);
            }
            int gi = (((b * NC + c) * NH) + h) * NW + w;   // even -> 8B aligned
            float2 r2 = *(const float2*)(re + gi);
            float2 i2 = *(const float2*)(img + gi);
            float2 o;
            o.x = n0 * id0 * (1.f - r2.x) + i2.x * r2.x;
            o.y = n1 * id1 * (1.f - r2.y) + i2.y * r2.y;
            *(float2*)(out + gi) = o;
        }
    }
}

__global__ __launch_bounds__(NT, 3) void gdfn_fused(
    const float* __restrict__ img, const float* __restrict__ noise,
    const float* __restrict__ re, const int* __restrict__ sel,
    const int* __restrict__ mixsel, float* __restrict__ out)
{
    const int b  = blockIdx.z;
    const int bx = blockIdx.x * BX;
    const int by = blockIdx.y * BY;
    const int tx = threadIdx.x, ty = threadIdx.y;
    const int tid = ty * BX + tx;

    if (!sel[b]) {  // uniform early-exit: pure copy (no barriers on this path)
        int h = by + ty, w = bx + tx;
        #pragma unroll
        for (int c = 0; c < NC; c++) {
            int gi = (((b * NC + c) * NH) + h) * NW + w;
            out[gi] = img[gi];
        }
        return;
    }

    __shared__ Smem S;
    const int mix = mixsel[b];
    const bool interior = (by >= 3) && (by + TY - 3 <= NH)
                       && (bx >= 3) && (bx + TX - 3 <= NW);
    if (interior) run_tile<true >(S, b, by, bx, tid, mix, img, noise, re, out);
    else          run_tile<false>(S, b, by, bx, tid, mix, img, noise, re, out);
}

extern "C" void kernel_launch(void* const* d_in, const int* in_sizes, int n_in,
                              void* d_out, int out_size)
{
    const float* img    = (const float*)d_in[0];
    const float* noise  = (const float*)d_in[1];
    const float* re     = (const float*)d_in[2];
    const int*   sel    = (const int*)d_in[3];
    const int*   mixsel = (const int*)d_in[4];
    float*       out    = (float*)d_out;

    dim3 blk(BX, BY), grd(NW / BX, NH / BY, NB);
    gdfn_fused<<<grd, blk>>>(img, noise, re, sel, mixsel, out);
}

// round 16
// speedup vs baseline: 1.0635x; 1.0635x over previous
#include <cuda_runtime.h>

#define NB 8
#define NC 3
#define NH 512
#define NW 512
#define HP 514
#define WP 514
#define BX 32
#define BY 16
#define NT 512                // 32x16 threads

// shared tile dims
#define TX (BX + 6)           // 38
#define TY (BY + 6)           // 22
#define RX (BX + 4)           // 36
#define RY (BY + 4)           // 20
#define MX (BX + 2)           // 34
#define MY (BY + 2)           // 18

// (0.5/var_ddof1)*log2e numerator: 4*log2e
#define CEXP 5.770780163555854f

struct alignas(16) Smem {
    float  sp[NC][TY][TX];     // img_p tile
    float  usum[TY][TX];       // channel sum of sp
    float  sr[RY][RX];         // img_r (zero outside image)
    float2 sstat[NC][RY][RX];  // (mean, a) per channel
    float  sm[MY][MX];         // img_3d_mod (zero outside image)
};                             // ~35.1 KB

// raw 2^x (MUFU.EX2); exp(-z) == ex2(-z*log2e), log2e folded into 'a'
static __device__ __forceinline__ float ex2f(float x)
{
    float r; asm("ex2.approx.f32 %0, %1;" : "=f"(r) : "f"(x)); return r;
}

// stage A: one img_r pixel + stats (R13-proven, 32-reg path)
template<bool IN>
static __device__ __forceinline__ void stageA(Smem& S, int i, int by, int bx)
{
    int ly = i / RX, lx = i - ly * RX;
    bool inimg = true;
    if (!IN) {
        int hh = by - 2 + ly, ww = bx - 2 + lx;
        inimg = (hh >= 0 && hh < NH && ww >= 0 && ww < NW);
    }
    float rv = 0.f;
    if (inimg) {
        float zmax[9];
        #pragma unroll
        for (int c = 0; c < NC; c++) {
            float x[9], s = 0.f, ss = 0.f;
            #pragma unroll
            for (int k = 0; k < 9; k++) {
                x[k] = S.sp[c][ly + k / 3][lx + k % 3];
                s += x[k];
                ss = fmaf(x[k], x[k], ss);
            }
            float mn = s * (1.f / 9.f);
            float a  = __fdividef(CEXP, fmaf(-s, mn, ss));
            S.sstat[c][ly][lx] = make_float2(mn, a);
            #pragma unroll
            for (int k = 0; k < 9; k++) {
                float d = x[k] - mn;
                float z = d * d * a;
                zmax[k] = (c == 0) ? z : fmaxf(zmax[k], z);
            }
        }
        float num = 0.f, den = 0.f;
        #pragma unroll
        for (int k = 0; k < 9; k++) {
            float m = ex2f(-zmax[k]);
            den += m;
            num = fmaf(S.usum[ly + k / 3][lx + k % 3], m, num);
        }
        rv = __fdividef(num, den);
    }
    S.sr[ly][lx] = rv;
}

// stage B: one PAIR of mod pixels (lx even) — R14-proven logic
template<bool IN>
static __device__ __forceinline__ void stageB2(Smem& S, int q, int by, int bx, int mix)
{
    int ly = q / (MX / 2);
    int lx = (q - ly * (MX / 2)) * 2;
    bool in0 = true, in1 = true;
    if (!IN) {
        int hh = by - 1 + ly, ww = bx - 1 + lx;
        bool hok = (hh >= 0 && hh < NH);
        in0 = hok && (ww >= 0) && (ww < NW);
        in1 = hok && (ww + 1 >= 0) && (ww + 1 < NW);
    }
    float2 ta[3], tb[3];                     // sr cols lx..lx+3, rows ly..ly+2
    #pragma unroll
    for (int i = 0; i < 3; i++) {
        ta[i] = *(const float2*)&S.sr[ly + i][lx];
        tb[i] = *(const float2*)&S.sr[ly + i][lx + 2];
    }
    // first-occurrence argmin/argmax for both pixels (k ascending, strict cmp)
    float vmin0, vmax0, vmin1, vmax1;
    int imin0 = 0, imax0 = 0, imin1 = 0, imax1 = 0;
    vmin0 = vmax0 = ta[0].x;
    vmin1 = vmax1 = ta[0].y;
    #pragma unroll
    for (int k = 1; k < 9; k++) {
        int i = k / 3, j = k % 3;
        float v0 = (j == 0) ? ta[i].x : ((j == 1) ? ta[i].y : tb[i].x);
        float v1 = (j == 0) ? ta[i].y : ((j == 1) ? tb[i].x : tb[i].y);
        if (v0 < vmin0) { vmin0 = v0; imin0 = k; }
        if (v0 > vmax0) { vmax0 = v0; imax0 = k; }
        if (v1 < vmin1) { vmin1 = v1; imin1 = k; }
        if (v1 > vmax1) { vmax1 = v1; imax1 = k; }
    }
    int ids0 = mix ? imax0 : imin0;
    int ids1 = mix ? imax1 : imin1;
    int ki0 = ids0 / 3, kj0 = ids0 % 3;
    int ki1 = ids1 / 3, kj1 = ids1 % 3;
    float zm0 = 0.f, zm1 = 0.f;
    #pragma unroll
    for (int c = 0; c < NC; c++) {
        float2 st0 = S.sstat[c][ly + 1][lx + 1];
        float2 st1 = S.sstat[c][ly + 1][lx + 2];
        float d0 = S.sp[c][ly + 1 + ki0][lx + 1 + kj0] - st0.x;
        zm0 = fmaxf(zm0, d0 * d0 * st0.y);
        float d1 = S.sp[c][ly + 1 + ki1][lx + 2 + kj1] - st1.x;
        zm1 = fmaxf(zm1, d1 * d1 * st1.y);
    }
    float mv0 = in0 ? ex2f(-zm0) : 0.f;
    float mv1 = in1 ? ex2f(-zm1) : 0.f;
    *(float2*)&S.sm[ly][lx] = make_float2(mv0, mv1);   // STS.64
}

template<bool IN>
static __device__ __forceinline__ void run_tile(
    Smem& S, int b, int by, int bx, int tid, int mix,
    const float* __restrict__ img, const float* __restrict__ noise,
    const float* __restrict__ re, float* __restrict__ out)
{
    // ---- load img_p tile ----
    if (IN) {
        // pixel-PAIR loading: 418 pairs, single balanced pass, float2 noise + STS.64
        if (tid < TY * (TX / 2)) {
            int ly = tid / (TX / 2);
            int lx = (tid - ly * (TX / 2)) * 2;     // even, 0..36
            int yp = by - 2 + ly, xp = bx - 2 + lx; // xp even -> noise 8B aligned
            int nbase = ((b * NC) * HP + yp) * WP + xp;
            int ibase = ((b * NC) * NH + (yp - 1)) * NW + (xp - 1);
            float2 v[NC];
            #pragma unroll
            for (int c = 0; c < NC; c++) {
                float2 n2 = *(const float2*)(noise + nbase + c * HP * WP);
                v[c].x = n2.x + img[ibase + c * NH * NW];
                v[c].y = n2.y + img[ibase + c * NH * NW + 1];
                *(float2*)&S.sp[c][ly][lx] = v[c];
            }
            *(float2*)&S.usum[ly][lx] =
                make_float2(v[0].x + v[1].x + v[2].x, v[0].y + v[1].y + v[2].y);
        }
    } else {
        for (int i = tid; i < TY * TX; i += NT) {
            int ly = i / TX, lx = i - ly * TX;
            int yp = by - 2 + ly, xp = bx - 2 + lx;
            float v0 = 0.f, v1 = 0.f, v2 = 0.f;
            if (yp >= 0 && yp < HP && xp >= 0 && xp < WP) {
                int nbase = ((b * NC) * HP + yp) * WP + xp;
                v0 = noise[nbase];
                v1 = noise[nbase + HP * WP];
                v2 = noise[nbase + 2 * HP * WP];
                if (yp >= 1 && yp <= NH && xp >= 1 && xp <= NW) {
                    int ibase = ((b * NC) * NH + (yp - 1)) * NW + (xp - 1);
                    v0 += img[ibase];
                    v1 += img[ibase + NH * NW];
                    v2 += img[ibase + 2 * NH * NW];
                }
            }
            S.sp[0][ly][lx] = v0;
            S.sp[1][ly][lx] = v1;
            S.sp[2][ly][lx] = v2;
            S.usum[ly][lx]  = v0 + v1 + v2;
        }
    }
    __syncthreads();

    // ---- stage A: 720 items, two passes (R13-proven) ----
    stageA<IN>(S, tid, by, bx);
    if (tid + NT < RY * RX) stageA<IN>(S, tid + NT, by, bx);
    __syncthreads();

    // ---- stage B: 306 pixel-pairs, single balanced pass ----
    if (tid < (MY * MX) / 2) stageB2<IN>(S, tid, by, bx, mix);
    __syncthreads();

    // ---- stage C: 256 pixel-pairs, float2 smem + gmem I/O ----
    if (tid < (BX / 2) * BY) {
        int ty  = tid >> 4;           // 0..15
        int tx2 = (tid & 15) * 2;     // even column 0..30
        float2 ma[3], mb[3];
        #pragma unroll
        for (int i = 0; i < 3; i++) {
            ma[i] = *(const float2*)&S.sm[ty + i][tx2];
            mb[i] = *(const float2*)&S.sm[ty + i][tx2 + 2];
        }
        float den0 = 0.f, den1 = 0.f;
        #pragma unroll
        for (int i = 0; i < 3; i++) {
            den0 += ma[i].x + ma[i].y + mb[i].x;
            den1 += ma[i].y + mb[i].x + mb[i].y;
        }
        float id0 = __fdividef(1.f, den0);
        float id1 = __fdividef(1.f, den1);
        const int h = by + ty, w = bx + tx2;
        #pragma unroll
        for (int c = 0; c < NC; c++) {
            float n0 = 0.f, n1 = 0.f;
            #pragma unroll
            for (int i = 0; i < 3; i++) {
                float2 p = *(const float2*)&S.sp[c][ty + 2 + i][tx2 + 2];
                float2 q = *(const float2*)&S.sp[c][ty + 2 + i][tx2 + 4];
                float t1 = p.y * ma[i].y;
                float t2 = q.x * mb[i].x;
                n0 += fmaf(p.x, ma[i].x, t1 + t2);
                n1 += fmaf(q.y, mb[i].y, t1 + t2);
            }
            int gi = (((b * NC + c) * NH) + h) * NW + w;   // even -> 8B aligned
            float2 r2 = *(const float2*)(re + gi);
            float2 i2 = *(const float2*)(img + gi);
            float2 o;
            o.x = n0 * id0 * (1.f - r2.x) + i2.x * r2.x;
            o.y = n1 * id1 * (1.f - r2.y) + i2.y * r2.y;
            *(float2*)(out + gi) = o;
        }
    }
}

__global__ __launch_bounds__(NT, 4) void gdfn_fused(
    const float* __restrict__ img, const float* __restrict__ noise,
    const float* __restrict__ re, const int* __restrict__ sel,
    const int* __restrict__ mixsel, float* __restrict__ out)
{
    const int b  = blockIdx.z;
    const int bx = blockIdx.x * BX;
    const int by = blockIdx.y * BY;
    const int tx = threadIdx.x, ty = threadIdx.y;
    const int tid = ty * BX + tx;

    if (!sel[b]) {  // uniform early-exit: pure copy (no barriers on this path)
        int h = by + ty, w = bx + tx;
        #pragma unroll
        for (int c = 0; c < NC; c++) {
            int gi = (((b * NC + c) * NH) + h) * NW + w;
            out[gi] = img[gi];
        }
        return;
    }

    __shared__ Smem S;
    const int mix = mixsel[b];
    const bool interior = (by >= 3) && (by + TY - 3 <= NH)
                       && (bx >= 3) && (bx + TX - 3 <= NW);
    if (interior) run_tile<true >(S, b, by, bx, tid, mix, img, noise, re, out);
    else          run_tile<false>(S, b, by, bx, tid, mix, img, noise, re, out);
}

extern "C" void kernel_launch(void* const* d_in, const int* in_sizes, int n_in,
                              void* d_out, int out_size)
{
    const float* img    = (const float*)d_in[0];
    const float* noise  = (const float*)d_in[1];
    const float* re     = (const float*)d_in[2];
    const int*   sel    = (const int*)d_in[3];
    const int*   mixsel = (const int*)d_in[4];
    float*       out    = (float*)d_out;

    dim3 blk(BX, BY), grd(NW / BX, NH / BY, NB);
    gdfn_fused<<<grd, blk>>>(img, noise, re, sel, mixsel, out);
}